// round 6
// baseline (speedup 1.0000x reference)
#include <cuda_runtime.h>
#include <cuda_bf16.h>
#include <cstdint>

#define NN 50000
#define EE 800000
#define HID 64

// ---------------- scratch (__device__ globals; no allocs allowed) ----------
__device__ float g_h[NN * HID];
__device__ float g_act[NN * HID];
__device__ int   g_cnt[NN];
__device__ int   g_off[NN + 1];
__device__ int   g_cur[NN];
__device__ float g_dinv[NN];
__device__ int   g_csrc[EE];
// Pre-transposed, bf16-split weights: Wt[n][k] (k contiguous)
__device__ uint16_t g_wt1h[64 * 512];
__device__ uint16_t g_wt1l[64 * 512];
__device__ uint16_t g_wt2h[64 * 64];
__device__ uint16_t g_wt2l[64 * 64];

// ---------------- helpers ---------------------------------------------------
__device__ __forceinline__ uint32_t cvt_bf16x2(float hi_elem, float lo_elem) {
    uint32_t r;
    asm("cvt.rn.bf16x2.f32 %0, %1, %2;" : "=r"(r) : "f"(hi_elem), "f"(lo_elem));
    return r;
}
__device__ __forceinline__ void split_pair(float x0, float x1,
                                           uint32_t& h, uint32_t& l) {
    h = cvt_bf16x2(x1, x0);
    float h0 = __uint_as_float(h << 16);
    float h1 = __uint_as_float(h & 0xffff0000u);
    l = cvt_bf16x2(x1 - h1, x0 - h0);
}
__device__ __forceinline__ void mma_bf16(float& d0, float& d1, float& d2, float& d3,
                                         uint32_t a0, uint32_t a1, uint32_t a2, uint32_t a3,
                                         uint32_t b0, uint32_t b1) {
    asm volatile("mma.sync.aligned.m16n8k16.row.col.f32.bf16.bf16.f32 "
                 "{%0,%1,%2,%3}, {%4,%5,%6,%7}, {%8,%9}, {%0,%1,%2,%3};"
                 : "+f"(d0), "+f"(d1), "+f"(d2), "+f"(d3)
                 : "r"(a0), "r"(a1), "r"(a2), "r"(a3), "r"(b0), "r"(b1));
}

// ---------------- CSR construction -----------------------------------------
__global__ void k_hist(const int* __restrict__ dst) {
    int e = blockIdx.x * blockDim.x + threadIdx.x;
    if (e < EE) atomicAdd(&g_cnt[dst[e]], 1);
}

__global__ void k_scan() {
    extern __shared__ int buf[];
    __shared__ int sm[1024];
    int t = threadIdx.x;
    for (int i = t; i < NN; i += 1024) buf[i] = g_cnt[i];
    __syncthreads();
    const int C = (NN + 1023) / 1024;
    int start = t * C, end = start + C;
    if (end > NN) end = NN;
    int sum = 0;
    for (int i = start; i < end; i++) sum += buf[i];
    sm[t] = sum;
    __syncthreads();
    for (int ofs = 1; ofs < 1024; ofs <<= 1) {
        int v = (t >= ofs) ? sm[t - ofs] : 0;
        __syncthreads();
        sm[t] += v;
        __syncthreads();
    }
    int base = sm[t] - sum;
    for (int i = start; i < end; i++) {
        int c = buf[i];
        buf[i] = base;
        base += c;
        g_dinv[i] = rsqrtf((float)(c + 1));
    }
    __syncthreads();
    for (int i = t; i < NN; i += 1024) {
        int o = buf[i];
        g_off[i] = o;
        g_cur[i] = o;
    }
    if (t == 0) g_off[NN] = EE;
}

__global__ void k_fill(const int* __restrict__ src, const int* __restrict__ dst) {
    int e = blockIdx.x * blockDim.x + threadIdx.x;
    if (e >= EE) return;
    int s = src[e], d = dst[e];
    int pos = atomicAdd(&g_cur[d], 1);
    g_csrc[pos] = s;
}

// ---------------- weight prep: transpose + bf16 hi/lo split -----------------
__global__ void k_prep(const float* __restrict__ W1, const float* __restrict__ W2) {
    int idx = blockIdx.x * blockDim.x + threadIdx.x;
    int total1 = 64 * 512;
    if (idx < total1) {
        int n = idx >> 9, k = idx & 511;
        float v = W1[k * 64 + n];
        uint16_t hs = __bfloat16_as_ushort(__float2bfloat16(v));
        float hf = __uint_as_float((uint32_t)hs << 16);
        uint16_t ls = __bfloat16_as_ushort(__float2bfloat16(v - hf));
        g_wt1h[idx] = hs;
        g_wt1l[idx] = ls;
    }
    if (idx < 64 * 64) {
        int n = idx >> 6, k = idx & 63;
        float v = W2[k * 64 + n];
        uint16_t hs = __bfloat16_as_ushort(__float2bfloat16(v));
        float hf = __uint_as_float((uint32_t)hs << 16);
        uint16_t ls = __bfloat16_as_ushort(__float2bfloat16(v - hf));
        g_wt2h[idx] = hs;
        g_wt2l[idx] = ls;
    }
}

// ---------------- HMMA bf16-split GEMM: OUT[n,64] = X[n,Kdim] @ W[Kdim,64] --
#define XST 40   // smem row stride (bf16 units)

__global__ __launch_bounds__(128, 5) void k_gemm(
    const float* __restrict__ X,
    const uint16_t* __restrict__ Wth, const uint16_t* __restrict__ Wtl,
    float* __restrict__ OUT, int n, int Kdim) {
    __shared__ uint16_t Xh[64 * XST], Xl[64 * XST];
    __shared__ uint16_t Wh[64 * XST], Wl[64 * XST];
    int tid = threadIdx.x;
    int wid = tid >> 5;
    int lane = tid & 31;
    int gid = lane >> 2;
    int q = lane & 3;
    int r0 = blockIdx.x * 64;
    int rb = wid * 16;

    int xrow = tid >> 3;
    int xkg = (tid & 7) * 4;
    int wn = tid >> 4;
    int wkg = tid & 15;

    const uint32_t* wh32 = (const uint32_t*)Wth;
    const uint32_t* wl32 = (const uint32_t*)Wtl;
    int wstride = Kdim >> 1;

    float acc[8][4];
#pragma unroll
    for (int t = 0; t < 8; t++)
#pragma unroll
        for (int c = 0; c < 4; c++) acc[t][c] = 0.f;

    int nch = Kdim >> 5;
    float4 px[4];
    uint32_t pwh[8], pwl[8];

#pragma unroll
    for (int j = 0; j < 4; j++) {
        int gr = r0 + xrow + j * 16;
        px[j] = (gr < n) ? *(const float4*)(X + (size_t)gr * Kdim + xkg)
                         : make_float4(0.f, 0.f, 0.f, 0.f);
    }
#pragma unroll
    for (int j = 0; j < 8; j++) {
        int nn = wn + j * 8;
        pwh[j] = wh32[nn * wstride + wkg];
        pwl[j] = wl32[nn * wstride + wkg];
    }

    for (int ch = 0; ch < nch; ch++) {
#pragma unroll
        for (int j = 0; j < 4; j++) {
            int row = xrow + j * 16;
            uint32_t h01, l01, h23, l23;
            split_pair(px[j].x, px[j].y, h01, l01);
            split_pair(px[j].z, px[j].w, h23, l23);
            uint32_t* dh = (uint32_t*)&Xh[row * XST + xkg];
            uint32_t* dl = (uint32_t*)&Xl[row * XST + xkg];
            dh[0] = h01; dh[1] = h23;
            dl[0] = l01; dl[1] = l23;
        }
#pragma unroll
        for (int j = 0; j < 8; j++) {
            int nn = wn + j * 8;
            *(uint32_t*)&Wh[nn * XST + wkg * 2] = pwh[j];
            *(uint32_t*)&Wl[nn * XST + wkg * 2] = pwl[j];
        }
        __syncthreads();

        if (ch + 1 < nch) {
            int k0 = (ch + 1) << 5;
#pragma unroll
            for (int j = 0; j < 4; j++) {
                int gr = r0 + xrow + j * 16;
                px[j] = (gr < n)
                    ? *(const float4*)(X + (size_t)gr * Kdim + k0 + xkg)
                    : make_float4(0.f, 0.f, 0.f, 0.f);
            }
#pragma unroll
            for (int j = 0; j < 8; j++) {
                int nn = wn + j * 8;
                pwh[j] = wh32[nn * wstride + (k0 >> 1) + wkg];
                pwl[j] = wl32[nn * wstride + (k0 >> 1) + wkg];
            }
        }

#pragma unroll
        for (int s = 0; s < 2; s++) {
            int kb = s * 16 + 2 * q;
            uint32_t ah0 = *(const uint32_t*)&Xh[(rb + gid) * XST + kb];
            uint32_t ah1 = *(const uint32_t*)&Xh[(rb + gid + 8) * XST + kb];
            uint32_t ah2 = *(const uint32_t*)&Xh[(rb + gid) * XST + kb + 8];
            uint32_t ah3 = *(const uint32_t*)&Xh[(rb + gid + 8) * XST + kb + 8];
            uint32_t al0 = *(const uint32_t*)&Xl[(rb + gid) * XST + kb];
            uint32_t al1 = *(const uint32_t*)&Xl[(rb + gid + 8) * XST + kb];
            uint32_t al2 = *(const uint32_t*)&Xl[(rb + gid) * XST + kb + 8];
            uint32_t al3 = *(const uint32_t*)&Xl[(rb + gid + 8) * XST + kb + 8];
#pragma unroll
            for (int nt = 0; nt < 8; nt++) {
                int ncol = nt * 8 + gid;
                uint32_t bh0 = *(const uint32_t*)&Wh[ncol * XST + kb];
                uint32_t bh1 = *(const uint32_t*)&Wh[ncol * XST + kb + 8];
                uint32_t bl0 = *(const uint32_t*)&Wl[ncol * XST + kb];
                uint32_t bl1 = *(const uint32_t*)&Wl[ncol * XST + kb + 8];
                mma_bf16(acc[nt][0], acc[nt][1], acc[nt][2], acc[nt][3],
                         ah0, ah1, ah2, ah3, bh0, bh1);
                mma_bf16(acc[nt][0], acc[nt][1], acc[nt][2], acc[nt][3],
                         ah0, ah1, ah2, ah3, bl0, bl1);
                mma_bf16(acc[nt][0], acc[nt][1], acc[nt][2], acc[nt][3],
                         al0, al1, al2, al3, bh0, bh1);
            }
        }
        __syncthreads();
    }

    int gr0 = r0 + rb + gid;
    int gr1 = gr0 + 8;
#pragma unroll
    for (int nt = 0; nt < 8; nt++) {
        int col = nt * 8 + 2 * q;
        if (gr0 < n)
            *(float2*)(OUT + (size_t)gr0 * HID + col) =
                make_float2(acc[nt][0], acc[nt][1]);
        if (gr1 < n)
            *(float2*)(OUT + (size_t)gr1 * HID + col) =
                make_float2(acc[nt][2], acc[nt][3]);
    }
}

// ---------------- gather aggregation ---------------------------------------
// norm computed inline: dinv[src]*dinv[dst] (dinv is L2-resident, 200KB)
__global__ void k_agg(const float* __restrict__ H, const float* __restrict__ bias,
                      float* __restrict__ OUT, int do_relu) {
    int gid = blockIdx.x * blockDim.x + threadIdx.x;
    int node = gid >> 3;
    if (node >= NN) return;
    int l = (gid & 7) * 8;

    float di = g_dinv[node];
    float sw = di * di;
    const float* hn = H + (size_t)node * HID + l;
    float4 a0 = *(const float4*)(hn);
    float4 a1 = *(const float4*)(hn + 4);
    float4 b0 = *(const float4*)(bias + l);
    float4 b1v = *(const float4*)(bias + l + 4);
    a0.x = a0.x * sw + b0.x;  a0.y = a0.y * sw + b0.y;
    a0.z = a0.z * sw + b0.z;  a0.w = a0.w * sw + b0.w;
    a1.x = a1.x * sw + b1v.x; a1.y = a1.y * sw + b1v.y;
    a1.z = a1.z * sw + b1v.z; a1.w = a1.w * sw + b1v.w;

    int e1 = g_off[node + 1];
    for (int e = g_off[node]; e < e1; e++) {
        int s = g_csrc[e];
        float w = g_dinv[s] * di;
        const float* hs = H + (size_t)s * HID + l;
        float4 v0 = *(const float4*)(hs);
        float4 v1 = *(const float4*)(hs + 4);
        a0.x += v0.x * w; a0.y += v0.y * w; a0.z += v0.z * w; a0.w += v0.w * w;
        a1.x += v1.x * w; a1.y += v1.y * w; a1.z += v1.z * w; a1.w += v1.w * w;
    }
    if (do_relu) {
        a0.x = fmaxf(a0.x, 0.f); a0.y = fmaxf(a0.y, 0.f);
        a0.z = fmaxf(a0.z, 0.f); a0.w = fmaxf(a0.w, 0.f);
        a1.x = fmaxf(a1.x, 0.f); a1.y = fmaxf(a1.y, 0.f);
        a1.z = fmaxf(a1.z, 0.f); a1.w = fmaxf(a1.w, 0.f);
    }
    float* on = OUT + (size_t)node * HID + l;
    *(float4*)(on) = a0;
    *(float4*)(on + 4) = a1;
}

extern "C" void kernel_launch(void* const* d_in, const int* in_sizes, int n_in,
                              void* d_out, int out_size) {
    const float* x  = (const float*)d_in[0];
    const int*   ei = (const int*)d_in[1];   // [2, E]: src row then dst row
    const float* W1 = (const float*)d_in[2];
    const float* b1 = (const float*)d_in[3];
    const float* W2 = (const float*)d_in[4];
    const float* b2 = (const float*)d_in[5];
    float* out = (float*)d_out;
    const int* src = ei;
    const int* dst = ei + EE;

    float *ph, *pact;
    void* pcnt;
    uint16_t *w1h, *w1l, *w2h, *w2l;
    cudaGetSymbolAddress((void**)&ph, g_h);
    cudaGetSymbolAddress((void**)&pact, g_act);
    cudaGetSymbolAddress(&pcnt, g_cnt);
    cudaGetSymbolAddress((void**)&w1h, g_wt1h);
    cudaGetSymbolAddress((void**)&w1l, g_wt1l);
    cudaGetSymbolAddress((void**)&w2h, g_wt2h);
    cudaGetSymbolAddress((void**)&w2l, g_wt2l);

    cudaFuncSetAttribute(k_scan, cudaFuncAttributeMaxDynamicSharedMemorySize,
                         NN * (int)sizeof(int));

    // Fork: CSR build chain runs concurrently with weight prep + GEMM1.
    // (Host-side stream/event objects leak across the handful of calls the
    //  harness makes — host RAM only, no device memory involved.)
    static cudaStream_t s2 = nullptr;
    static cudaEvent_t evFork = nullptr, evJoin = nullptr;
    if (!s2) {
        cudaStreamCreateWithFlags(&s2, cudaStreamNonBlocking);
        cudaEventCreateWithFlags(&evFork, cudaEventDisableTiming);
        cudaEventCreateWithFlags(&evJoin, cudaEventDisableTiming);
    }

    cudaEventRecord(evFork, 0);
    cudaStreamWaitEvent(s2, evFork, 0);

    // branch A (s2): CSR by dst
    cudaMemsetAsync(pcnt, 0, NN * sizeof(int), s2);
    k_hist<<<(EE + 255) / 256, 256, 0, s2>>>(dst);
    k_scan<<<1, 1024, NN * sizeof(int), s2>>>();
    k_fill<<<(EE + 255) / 256, 256, 0, s2>>>(src, dst);
    cudaEventRecord(evJoin, s2);

    // branch B (main): weight prep + layer-1 GEMM
    k_prep<<<(64 * 512 + 255) / 256, 256>>>(W1, W2);
    k_gemm<<<(NN + 63) / 64, 128>>>(x, w1h, w1l, ph, NN, 512);

    // join, then the serial tail
    cudaStreamWaitEvent(0, evJoin, 0);
    k_agg<<<(NN * 8 + 255) / 256, 256>>>(ph, b1, pact, 1);
    k_gemm<<<(NN + 63) / 64, 128>>>(pact, w2h, w2l, ph, NN, HID);
    k_agg<<<(NN * 8 + 255) / 256, 256>>>(ph, b2, out, 0);
}

// round 7
// speedup vs baseline: 1.2798x; 1.2798x over previous
#include <cuda_runtime.h>
#include <cuda_bf16.h>
#include <cstdint>

#define NN 50000
#define EE 800000
#define HID 64

// ---------------- scratch (__device__ globals; no allocs allowed) ----------
__device__ float g_h[NN * HID];
__device__ float g_act[NN * HID];
__device__ int   g_cnt[NN];
__device__ int   g_off[NN + 1];
__device__ int   g_cur[NN];
__device__ float g_dinv[NN];
__device__ int   g_csrc[EE];
// Pre-transposed, bf16-split weights: Wt[n][k] (k contiguous)
__device__ uint16_t g_wt1h[64 * 512];
__device__ uint16_t g_wt1l[64 * 512];
__device__ uint16_t g_wt2h[64 * 64];
__device__ uint16_t g_wt2l[64 * 64];

// ---------------- helpers ---------------------------------------------------
__device__ __forceinline__ uint32_t smem_u32(const void* p) {
    uint32_t a;
    asm("{ .reg .u64 t; cvta.to.shared.u64 t, %1; cvt.u32.u64 %0, t; }"
        : "=r"(a) : "l"(p));
    return a;
}
__device__ __forceinline__ uint32_t cvt_bf16x2(float hi_elem, float lo_elem) {
    uint32_t r;
    asm("cvt.rn.bf16x2.f32 %0, %1, %2;" : "=r"(r) : "f"(hi_elem), "f"(lo_elem));
    return r;
}
__device__ __forceinline__ void split_pair(float x0, float x1,
                                           uint32_t& h, uint32_t& l) {
    h = cvt_bf16x2(x1, x0);
    float h0 = __uint_as_float(h << 16);
    float h1 = __uint_as_float(h & 0xffff0000u);
    l = cvt_bf16x2(x1 - h1, x0 - h0);
}
__device__ __forceinline__ void mma_bf16(float& d0, float& d1, float& d2, float& d3,
                                         uint32_t a0, uint32_t a1, uint32_t a2, uint32_t a3,
                                         uint32_t b0, uint32_t b1) {
    asm volatile("mma.sync.aligned.m16n8k16.row.col.f32.bf16.bf16.f32 "
                 "{%0,%1,%2,%3}, {%4,%5,%6,%7}, {%8,%9}, {%0,%1,%2,%3};"
                 : "+f"(d0), "+f"(d1), "+f"(d2), "+f"(d3)
                 : "r"(a0), "r"(a1), "r"(a2), "r"(a3), "r"(b0), "r"(b1));
}
__device__ __forceinline__ void ldsm_x4(uint32_t& r0, uint32_t& r1,
                                        uint32_t& r2, uint32_t& r3, uint32_t addr) {
    asm volatile("ldmatrix.sync.aligned.m8n8.x4.shared.b16 {%0,%1,%2,%3}, [%4];"
                 : "=r"(r0), "=r"(r1), "=r"(r2), "=r"(r3) : "r"(addr));
}

// ---------------- CSR construction -----------------------------------------
__global__ void k_hist(const int* __restrict__ dst) {
    int e = blockIdx.x * blockDim.x + threadIdx.x;
    if (e < EE) atomicAdd(&g_cnt[dst[e]], 1);
}

__global__ void k_scan() {
    extern __shared__ int buf[];
    __shared__ int sm[1024];
    int t = threadIdx.x;
    for (int i = t; i < NN; i += 1024) buf[i] = g_cnt[i];
    __syncthreads();
    const int C = (NN + 1023) / 1024;
    int start = t * C, end = start + C;
    if (end > NN) end = NN;
    int sum = 0;
    for (int i = start; i < end; i++) sum += buf[i];
    sm[t] = sum;
    __syncthreads();
    for (int ofs = 1; ofs < 1024; ofs <<= 1) {
        int v = (t >= ofs) ? sm[t - ofs] : 0;
        __syncthreads();
        sm[t] += v;
        __syncthreads();
    }
    int base = sm[t] - sum;
    for (int i = start; i < end; i++) {
        int c = buf[i];
        buf[i] = base;
        base += c;
        g_dinv[i] = rsqrtf((float)(c + 1));
    }
    __syncthreads();
    for (int i = t; i < NN; i += 1024) {
        int o = buf[i];
        g_off[i] = o;
        g_cur[i] = o;
    }
    if (t == 0) g_off[NN] = EE;
}

__global__ void k_fill(const int* __restrict__ src, const int* __restrict__ dst) {
    int e = blockIdx.x * blockDim.x + threadIdx.x;
    if (e >= EE) return;
    int s = src[e], d = dst[e];
    int pos = atomicAdd(&g_cur[d], 1);
    g_csrc[pos] = s;
}

// ------- weight prep: coalesced smem-tile transpose + bf16 split, + zero cnt
// grid = 36 blocks of 256 (32x8). Blocks 0-31: W1 (16 k-tiles x 2 n-tiles).
// Blocks 32-35: W2 (2x2 tiles).
__global__ void k_prep(const float* __restrict__ W1, const float* __restrict__ W2) {
    __shared__ uint16_t th[32][33], tl[32][33];
    int b = blockIdx.x;
    int tx = threadIdx.x & 31, ty = threadIdx.x >> 5;

    // fold in: zero the histogram counters
    for (int i = b * 256 + threadIdx.x; i < NN; i += 36 * 256) g_cnt[i] = 0;

    const float* W;
    uint16_t *oh, *ol;
    int kt, ntile, Kd;
    if (b < 32) { W = W1; oh = g_wt1h; ol = g_wt1l; kt = b >> 1; ntile = b & 1; Kd = 512; }
    else        { W = W2; oh = g_wt2h; ol = g_wt2l; kt = (b - 32) >> 1; ntile = (b - 32) & 1; Kd = 64; }

#pragma unroll
    for (int j = 0; j < 4; j++) {
        int k = kt * 32 + ty + j * 8;
        int n = ntile * 32 + tx;
        float v = W[k * 64 + n];                 // coalesced read
        uint16_t hs = __bfloat16_as_ushort(__float2bfloat16(v));
        float hf = __uint_as_float((uint32_t)hs << 16);
        uint16_t ls = __bfloat16_as_ushort(__float2bfloat16(v - hf));
        th[ty + j * 8][tx] = hs;
        tl[ty + j * 8][tx] = ls;
    }
    __syncthreads();
#pragma unroll
    for (int j = 0; j < 4; j++) {
        int n = ntile * 32 + ty + j * 8;
        int k = kt * 32 + tx;
        oh[n * Kd + k] = th[tx][ty + j * 8];     // coalesced write
        ol[n * Kd + k] = tl[tx][ty + j * 8];
    }
}

// ---------------- HMMA bf16-split GEMM (ldmatrix fragments) -----------------
// OUT[n,64] = X[n,Kdim] @ W[Kdim,64]. Block 128 thr (4 warps), 64x64 tile,
// K-chunks of 32. 3 products: Ah*Bh + Ah*Bl + Al*Bh, fp32 accum.
#define XST 40   // smem row stride (uint16): 80B = 5*16B -> LDSM conflict-free

__global__ __launch_bounds__(128, 4) void k_gemm(
    const float* __restrict__ X,
    const uint16_t* __restrict__ Wth, const uint16_t* __restrict__ Wtl,
    float* __restrict__ OUT, int n, int Kdim) {
    __shared__ __align__(16) uint16_t Xh[64 * XST], Xl[64 * XST];
    __shared__ __align__(16) uint16_t Wh[64 * XST], Wl[64 * XST];
    int tid = threadIdx.x;
    int wid = tid >> 5;
    int lane = tid & 31;
    int gid = lane >> 2;     // epilogue row/col within tile
    int q = lane & 3;
    int r0 = blockIdx.x * 64;
    int rb = wid * 16;

    // staging coords
    int xrow = tid >> 3;
    int xkg = (tid & 7) * 4;
    int wn = tid >> 4;
    int wkg = tid & 15;

    // ldmatrix lane->row mapping
    int g8 = lane >> 3, lr = lane & 7;
    int aoff = (rb + lr + (g8 & 1) * 8) * XST + (g8 >> 1) * 8;
    int boff0 = (lr + (g8 >> 1) * 8) * XST + (g8 & 1) * 8;   // pair p adds 16p*XST
    uint32_t xh_b = smem_u32(Xh), xl_b = smem_u32(Xl);
    uint32_t wh_b = smem_u32(Wh), wl_b = smem_u32(Wl);

    const uint32_t* wh32 = (const uint32_t*)Wth;
    const uint32_t* wl32 = (const uint32_t*)Wtl;
    int wstride = Kdim >> 1;

    float acc[8][4];
#pragma unroll
    for (int t = 0; t < 8; t++)
#pragma unroll
        for (int c = 0; c < 4; c++) acc[t][c] = 0.f;

    int nch = Kdim >> 5;
    float4 px[4];
    uint32_t pwh[8], pwl[8];

#pragma unroll
    for (int j = 0; j < 4; j++) {
        int gr = r0 + xrow + j * 16;
        px[j] = (gr < n) ? *(const float4*)(X + (size_t)gr * Kdim + xkg)
                         : make_float4(0.f, 0.f, 0.f, 0.f);
    }
#pragma unroll
    for (int j = 0; j < 8; j++) {
        int nn = wn + j * 8;
        pwh[j] = wh32[nn * wstride + wkg];
        pwl[j] = wl32[nn * wstride + wkg];
    }

    for (int ch = 0; ch < nch; ch++) {
#pragma unroll
        for (int j = 0; j < 4; j++) {
            int row = xrow + j * 16;
            uint32_t h01, l01, h23, l23;
            split_pair(px[j].x, px[j].y, h01, l01);
            split_pair(px[j].z, px[j].w, h23, l23);
            uint32_t* dh = (uint32_t*)&Xh[row * XST + xkg];
            uint32_t* dl = (uint32_t*)&Xl[row * XST + xkg];
            dh[0] = h01; dh[1] = h23;
            dl[0] = l01; dl[1] = l23;
        }
#pragma unroll
        for (int j = 0; j < 8; j++) {
            int nn = wn + j * 8;
            *(uint32_t*)&Wh[nn * XST + wkg * 2] = pwh[j];
            *(uint32_t*)&Wl[nn * XST + wkg * 2] = pwl[j];
        }
        __syncthreads();

        if (ch + 1 < nch) {
            int k0 = (ch + 1) << 5;
#pragma unroll
            for (int j = 0; j < 4; j++) {
                int gr = r0 + xrow + j * 16;
                px[j] = (gr < n)
                    ? *(const float4*)(X + (size_t)gr * Kdim + k0 + xkg)
                    : make_float4(0.f, 0.f, 0.f, 0.f);
            }
#pragma unroll
            for (int j = 0; j < 8; j++) {
                int nn = wn + j * 8;
                pwh[j] = wh32[nn * wstride + (k0 >> 1) + wkg];
                pwl[j] = wl32[nn * wstride + (k0 >> 1) + wkg];
            }
        }

#pragma unroll
        for (int s = 0; s < 2; s++) {
            uint32_t ah[4], al[4];
            ldsm_x4(ah[0], ah[1], ah[2], ah[3], xh_b + 2 * (aoff + s * 16));
            ldsm_x4(al[0], al[1], al[2], al[3], xl_b + 2 * (aoff + s * 16));
#pragma unroll
            for (int p = 0; p < 4; p++) {
                int bo = boff0 + p * 16 * XST + s * 16;
                uint32_t bh[4], bl[4];
                ldsm_x4(bh[0], bh[1], bh[2], bh[3], wh_b + 2 * bo);
                ldsm_x4(bl[0], bl[1], bl[2], bl[3], wl_b + 2 * bo);
                int t0 = 2 * p, t1 = 2 * p + 1;
                mma_bf16(acc[t0][0], acc[t0][1], acc[t0][2], acc[t0][3],
                         ah[0], ah[1], ah[2], ah[3], bh[0], bh[1]);
                mma_bf16(acc[t0][0], acc[t0][1], acc[t0][2], acc[t0][3],
                         ah[0], ah[1], ah[2], ah[3], bl[0], bl[1]);
                mma_bf16(acc[t0][0], acc[t0][1], acc[t0][2], acc[t0][3],
                         al[0], al[1], al[2], al[3], bh[0], bh[1]);
                mma_bf16(acc[t1][0], acc[t1][1], acc[t1][2], acc[t1][3],
                         ah[0], ah[1], ah[2], ah[3], bh[2], bh[3]);
                mma_bf16(acc[t1][0], acc[t1][1], acc[t1][2], acc[t1][3],
                         ah[0], ah[1], ah[2], ah[3], bl[2], bl[3]);
                mma_bf16(acc[t1][0], acc[t1][1], acc[t1][2], acc[t1][3],
                         al[0], al[1], al[2], al[3], bh[2], bh[3]);
            }
        }
        __syncthreads();
    }

    int gr0 = r0 + rb + gid;
    int gr1 = gr0 + 8;
#pragma unroll
    for (int nt = 0; nt < 8; nt++) {
        int col = nt * 8 + 2 * q;
        if (gr0 < n)
            *(float2*)(OUT + (size_t)gr0 * HID + col) =
                make_float2(acc[nt][0], acc[nt][1]);
        if (gr1 < n)
            *(float2*)(OUT + (size_t)gr1 * HID + col) =
                make_float2(acc[nt][2], acc[nt][3]);
    }
}

// ---------------- gather aggregation: one warp per node ---------------------
// out[i] = [relu]( sum_{e: dst=i} H[src_e]*dinv[s]*dinv[i] + dinv[i]^2*H[i] + b )
__global__ void k_agg(const float* __restrict__ H, const float* __restrict__ bias,
                      float* __restrict__ OUT, int do_relu) {
    int node = (blockIdx.x * blockDim.x + threadIdx.x) >> 5;
    if (node >= NN) return;
    int lane = threadIdx.x & 31;
    int l = lane * 2;

    float di = g_dinv[node];
    float sw = di * di;
    float2 a = *(const float2*)(H + (size_t)node * HID + l);
    float2 b = *(const float2*)(bias + l);
    a.x = a.x * sw + b.x;
    a.y = a.y * sw + b.y;

    int e = g_off[node], e1 = g_off[node + 1];
    int sNext = (e < e1) ? g_csrc[e] : 0;
    while (e < e1) {
        int s = sNext;
        e++;
        if (e < e1) sNext = g_csrc[e];
        float w = g_dinv[s] * di;
        float2 v = *(const float2*)(H + (size_t)s * HID + l);
        a.x += v.x * w;
        a.y += v.y * w;
    }
    if (do_relu) {
        a.x = fmaxf(a.x, 0.f);
        a.y = fmaxf(a.y, 0.f);
    }
    *(float2*)(OUT + (size_t)node * HID + l) = a;
}

extern "C" void kernel_launch(void* const* d_in, const int* in_sizes, int n_in,
                              void* d_out, int out_size) {
    const float* x  = (const float*)d_in[0];
    const int*   ei = (const int*)d_in[1];   // [2, E]: src row then dst row
    const float* W1 = (const float*)d_in[2];
    const float* b1 = (const float*)d_in[3];
    const float* W2 = (const float*)d_in[4];
    const float* b2 = (const float*)d_in[5];
    float* out = (float*)d_out;
    const int* src = ei;
    const int* dst = ei + EE;

    float *ph, *pact;
    uint16_t *w1h, *w1l, *w2h, *w2l;
    cudaGetSymbolAddress((void**)&ph, g_h);
    cudaGetSymbolAddress((void**)&pact, g_act);
    cudaGetSymbolAddress((void**)&w1h, g_wt1h);
    cudaGetSymbolAddress((void**)&w1l, g_wt1l);
    cudaGetSymbolAddress((void**)&w2h, g_wt2h);
    cudaGetSymbolAddress((void**)&w2l, g_wt2l);

    cudaFuncSetAttribute(k_scan, cudaFuncAttributeMaxDynamicSharedMemorySize,
                         NN * (int)sizeof(int));

    // Serial pipeline (stream fork regressed in R6 — L2 contention)
    k_prep<<<36, 256>>>(W1, W2);                       // also zeros g_cnt
    k_hist<<<(EE + 255) / 256, 256>>>(dst);
    k_scan<<<1, 1024, NN * sizeof(int)>>>();
    k_fill<<<(EE + 255) / 256, 256>>>(src, dst);

    // Layer 1
    k_gemm<<<(NN + 63) / 64, 128>>>(x, w1h, w1l, ph, NN, 512);
    k_agg<<<(NN * 32 + 255) / 256, 256>>>(ph, b1, pact, 1);
    // Layer 2
    k_gemm<<<(NN + 63) / 64, 128>>>(pact, w2h, w2l, ph, NN, HID);
    k_agg<<<(NN * 32 + 255) / 256, 256>>>(ph, b2, out, 0);
}

// round 8
// speedup vs baseline: 1.3139x; 1.0266x over previous
#include <cuda_runtime.h>
#include <cuda_bf16.h>
#include <cstdint>

#define NN 50000
#define EE 800000
#define HID 64

// ---------------- scratch (__device__ globals; no allocs allowed) ----------
__device__ float g_h[NN * HID];
__device__ float g_act[NN * HID];
__device__ int   g_cnt[NN];     // zero at load; re-zeroed by k_fill each run
__device__ int   g_off[NN + 1];
__device__ int   g_cur[NN];
__device__ float g_dinv[NN];
__device__ int   g_csrc[EE];
// Pre-transposed, bf16-split weights: Wt[n][k] (k contiguous)
__device__ uint16_t g_wt1h[64 * 512];
__device__ uint16_t g_wt1l[64 * 512];
__device__ uint16_t g_wt2h[64 * 64];
__device__ uint16_t g_wt2l[64 * 64];

// ---------------- helpers ---------------------------------------------------
__device__ __forceinline__ uint32_t smem_u32(const void* p) {
    uint32_t a;
    asm("{ .reg .u64 t; cvta.to.shared.u64 t, %1; cvt.u32.u64 %0, t; }"
        : "=r"(a) : "l"(p));
    return a;
}
__device__ __forceinline__ uint32_t cvt_bf16x2(float hi_elem, float lo_elem) {
    uint32_t r;
    asm("cvt.rn.bf16x2.f32 %0, %1, %2;" : "=r"(r) : "f"(hi_elem), "f"(lo_elem));
    return r;
}
__device__ __forceinline__ void split_pair(float x0, float x1,
                                           uint32_t& h, uint32_t& l) {
    h = cvt_bf16x2(x1, x0);
    float h0 = __uint_as_float(h << 16);
    float h1 = __uint_as_float(h & 0xffff0000u);
    l = cvt_bf16x2(x1 - h1, x0 - h0);
}
__device__ __forceinline__ void mma_bf16(float& d0, float& d1, float& d2, float& d3,
                                         uint32_t a0, uint32_t a1, uint32_t a2, uint32_t a3,
                                         uint32_t b0, uint32_t b1) {
    asm volatile("mma.sync.aligned.m16n8k16.row.col.f32.bf16.bf16.f32 "
                 "{%0,%1,%2,%3}, {%4,%5,%6,%7}, {%8,%9}, {%0,%1,%2,%3};"
                 : "+f"(d0), "+f"(d1), "+f"(d2), "+f"(d3)
                 : "r"(a0), "r"(a1), "r"(a2), "r"(a3), "r"(b0), "r"(b1));
}
__device__ __forceinline__ void ldsm_x4(uint32_t& r0, uint32_t& r1,
                                        uint32_t& r2, uint32_t& r3, uint32_t addr) {
    asm volatile("ldmatrix.sync.aligned.m8n8.x4.shared.b16 {%0,%1,%2,%3}, [%4];"
                 : "=r"(r0), "=r"(r1), "=r"(r2), "=r"(r3) : "r"(addr));
}

// ---------------- CSR construction -----------------------------------------
__global__ void k_hist(const int* __restrict__ dst) {
    int e = blockIdx.x * blockDim.x + threadIdx.x;
    if (e < EE) atomicAdd(&g_cnt[dst[e]], 1);
}

__global__ void k_scan() {
    extern __shared__ int buf[];
    __shared__ int sm[1024];
    int t = threadIdx.x;
    for (int i = t; i < NN; i += 1024) buf[i] = g_cnt[i];
    __syncthreads();
    const int C = (NN + 1023) / 1024;
    int start = t * C, end = start + C;
    if (end > NN) end = NN;
    int sum = 0;
    for (int i = start; i < end; i++) sum += buf[i];
    sm[t] = sum;
    __syncthreads();
    for (int ofs = 1; ofs < 1024; ofs <<= 1) {
        int v = (t >= ofs) ? sm[t - ofs] : 0;
        __syncthreads();
        sm[t] += v;
        __syncthreads();
    }
    int base = sm[t] - sum;
    for (int i = start; i < end; i++) {
        int c = buf[i];
        buf[i] = base;
        base += c;
        g_dinv[i] = rsqrtf((float)(c + 1));
    }
    __syncthreads();
    for (int i = t; i < NN; i += 1024) {
        int o = buf[i];
        g_off[i] = o;
        g_cur[i] = o;
    }
    if (t == 0) g_off[NN] = EE;
}

// fill CSR; also re-zero g_cnt for the next graph replay (cnt is dead here)
__global__ void k_fill(const int* __restrict__ src, const int* __restrict__ dst) {
    int e = blockIdx.x * blockDim.x + threadIdx.x;
    if (e < NN) g_cnt[e] = 0;
    if (e >= EE) return;
    int s = src[e], d = dst[e];
    int pos = atomicAdd(&g_cur[d], 1);
    g_csrc[pos] = s;
}

// ------- weight prep: coalesced smem-tile transpose + bf16 split ------------
__global__ void k_prep(const float* __restrict__ W1, const float* __restrict__ W2) {
    __shared__ uint16_t th[32][33], tl[32][33];
    int b = blockIdx.x;
    int tx = threadIdx.x & 31, ty = threadIdx.x >> 5;

    const float* W;
    uint16_t *oh, *ol;
    int kt, ntile, Kd;
    if (b < 32) { W = W1; oh = g_wt1h; ol = g_wt1l; kt = b >> 1; ntile = b & 1; Kd = 512; }
    else        { W = W2; oh = g_wt2h; ol = g_wt2l; kt = (b - 32) >> 1; ntile = (b - 32) & 1; Kd = 64; }

#pragma unroll
    for (int j = 0; j < 4; j++) {
        int k = kt * 32 + ty + j * 8;
        int n = ntile * 32 + tx;
        float v = W[k * 64 + n];
        uint16_t hs = __bfloat16_as_ushort(__float2bfloat16(v));
        float hf = __uint_as_float((uint32_t)hs << 16);
        uint16_t ls = __bfloat16_as_ushort(__float2bfloat16(v - hf));
        th[ty + j * 8][tx] = hs;
        tl[ty + j * 8][tx] = ls;
    }
    __syncthreads();
#pragma unroll
    for (int j = 0; j < 4; j++) {
        int n = ntile * 32 + ty + j * 8;
        int k = kt * 32 + tx;
        oh[n * Kd + k] = th[tx][ty + j * 8];
        ol[n * Kd + k] = tl[tx][ty + j * 8];
    }
}

// ---------------- HMMA bf16-split GEMM (ldmatrix fragments) -----------------
#define XST 40   // smem row stride (uint16): 80B = 5*16B -> LDSM conflict-free

__global__ __launch_bounds__(128, 4) void k_gemm(
    const float* __restrict__ X,
    const uint16_t* __restrict__ Wth, const uint16_t* __restrict__ Wtl,
    float* __restrict__ OUT, int n, int Kdim) {
    __shared__ __align__(16) uint16_t Xh[64 * XST], Xl[64 * XST];
    __shared__ __align__(16) uint16_t Wh[64 * XST], Wl[64 * XST];
    int tid = threadIdx.x;
    int wid = tid >> 5;
    int lane = tid & 31;
    int gid = lane >> 2;
    int q = lane & 3;
    int r0 = blockIdx.x * 64;
    int rb = wid * 16;

    int xrow = tid >> 3;
    int xkg = (tid & 7) * 4;
    int wn = tid >> 4;
    int wkg = tid & 15;

    int g8 = lane >> 3, lr = lane & 7;
    int aoff = (rb + lr + (g8 & 1) * 8) * XST + (g8 >> 1) * 8;
    int boff0 = (lr + (g8 >> 1) * 8) * XST + (g8 & 1) * 8;
    uint32_t xh_b = smem_u32(Xh), xl_b = smem_u32(Xl);
    uint32_t wh_b = smem_u32(Wh), wl_b = smem_u32(Wl);

    const uint32_t* wh32 = (const uint32_t*)Wth;
    const uint32_t* wl32 = (const uint32_t*)Wtl;
    int wstride = Kdim >> 1;

    float acc[8][4];
#pragma unroll
    for (int t = 0; t < 8; t++)
#pragma unroll
        for (int c = 0; c < 4; c++) acc[t][c] = 0.f;

    int nch = Kdim >> 5;
    float4 px[4];
    uint32_t pwh[8], pwl[8];

#pragma unroll
    for (int j = 0; j < 4; j++) {
        int gr = r0 + xrow + j * 16;
        px[j] = (gr < n) ? *(const float4*)(X + (size_t)gr * Kdim + xkg)
                         : make_float4(0.f, 0.f, 0.f, 0.f);
    }
#pragma unroll
    for (int j = 0; j < 8; j++) {
        int nn = wn + j * 8;
        pwh[j] = wh32[nn * wstride + wkg];
        pwl[j] = wl32[nn * wstride + wkg];
    }

    for (int ch = 0; ch < nch; ch++) {
#pragma unroll
        for (int j = 0; j < 4; j++) {
            int row = xrow + j * 16;
            uint32_t h01, l01, h23, l23;
            split_pair(px[j].x, px[j].y, h01, l01);
            split_pair(px[j].z, px[j].w, h23, l23);
            uint32_t* dh = (uint32_t*)&Xh[row * XST + xkg];
            uint32_t* dl = (uint32_t*)&Xl[row * XST + xkg];
            dh[0] = h01; dh[1] = h23;
            dl[0] = l01; dl[1] = l23;
        }
#pragma unroll
        for (int j = 0; j < 8; j++) {
            int nn = wn + j * 8;
            *(uint32_t*)&Wh[nn * XST + wkg * 2] = pwh[j];
            *(uint32_t*)&Wl[nn * XST + wkg * 2] = pwl[j];
        }
        __syncthreads();

        if (ch + 1 < nch) {
            int k0 = (ch + 1) << 5;
#pragma unroll
            for (int j = 0; j < 4; j++) {
                int gr = r0 + xrow + j * 16;
                px[j] = (gr < n)
                    ? *(const float4*)(X + (size_t)gr * Kdim + k0 + xkg)
                    : make_float4(0.f, 0.f, 0.f, 0.f);
            }
#pragma unroll
            for (int j = 0; j < 8; j++) {
                int nn = wn + j * 8;
                pwh[j] = wh32[nn * wstride + (k0 >> 1) + wkg];
                pwl[j] = wl32[nn * wstride + (k0 >> 1) + wkg];
            }
        }

#pragma unroll
        for (int s = 0; s < 2; s++) {
            uint32_t ah[4], al[4];
            ldsm_x4(ah[0], ah[1], ah[2], ah[3], xh_b + 2 * (aoff + s * 16));
            ldsm_x4(al[0], al[1], al[2], al[3], xl_b + 2 * (aoff + s * 16));
#pragma unroll
            for (int p = 0; p < 4; p++) {
                int bo = boff0 + p * 16 * XST + s * 16;
                uint32_t bh[4], bl[4];
                ldsm_x4(bh[0], bh[1], bh[2], bh[3], wh_b + 2 * bo);
                ldsm_x4(bl[0], bl[1], bl[2], bl[3], wl_b + 2 * bo);
                int t0 = 2 * p, t1 = 2 * p + 1;
                mma_bf16(acc[t0][0], acc[t0][1], acc[t0][2], acc[t0][3],
                         ah[0], ah[1], ah[2], ah[3], bh[0], bh[1]);
                mma_bf16(acc[t0][0], acc[t0][1], acc[t0][2], acc[t0][3],
                         ah[0], ah[1], ah[2], ah[3], bl[0], bl[1]);
                mma_bf16(acc[t0][0], acc[t0][1], acc[t0][2], acc[t0][3],
                         al[0], al[1], al[2], al[3], bh[0], bh[1]);
                mma_bf16(acc[t1][0], acc[t1][1], acc[t1][2], acc[t1][3],
                         ah[0], ah[1], ah[2], ah[3], bh[2], bh[3]);
                mma_bf16(acc[t1][0], acc[t1][1], acc[t1][2], acc[t1][3],
                         ah[0], ah[1], ah[2], ah[3], bl[2], bl[3]);
                mma_bf16(acc[t1][0], acc[t1][1], acc[t1][2], acc[t1][3],
                         al[0], al[1], al[2], al[3], bh[2], bh[3]);
            }
        }
        __syncthreads();
    }

    int gr0 = r0 + rb + gid;
    int gr1 = gr0 + 8;
#pragma unroll
    for (int nt = 0; nt < 8; nt++) {
        int col = nt * 8 + 2 * q;
        if (gr0 < n)
            *(float2*)(OUT + (size_t)gr0 * HID + col) =
                make_float2(acc[nt][0], acc[nt][1]);
        if (gr1 < n)
            *(float2*)(OUT + (size_t)gr1 * HID + col) =
                make_float2(acc[nt][2], acc[nt][3]);
    }
}

// ------- gather aggregation: warp per node, half-warp per edge, float4 ------
// out[i] = [relu]( sum_{e: dst=i} H[src_e]*dinv[s]*dinv[i] + dinv[i]^2*H[i] + b )
__global__ void k_agg(const float* __restrict__ H, const float* __restrict__ bias,
                      float* __restrict__ OUT, int do_relu) {
    int node = (blockIdx.x * blockDim.x + threadIdx.x) >> 5;
    if (node >= NN) return;
    int lane = threadIdx.x & 31;
    int half = lane >> 4;          // 0 or 1
    int l = (lane & 15) * 4;       // feature offset (float4)

    float di = g_dinv[node];
    float4 a = make_float4(0.f, 0.f, 0.f, 0.f);
    if (half == 0) {
        float sw = di * di;
        float4 hv = *(const float4*)(H + (size_t)node * HID + l);
        float4 b = *(const float4*)(bias + l);
        a.x = hv.x * sw + b.x;
        a.y = hv.y * sw + b.y;
        a.z = hv.z * sw + b.z;
        a.w = hv.w * sw + b.w;
    }

    int e1 = g_off[node + 1];
    for (int e = g_off[node] + half; e < e1; e += 2) {
        int s = g_csrc[e];
        float w = g_dinv[s] * di;
        float4 v = *(const float4*)(H + (size_t)s * HID + l);
        a.x += v.x * w;
        a.y += v.y * w;
        a.z += v.z * w;
        a.w += v.w * w;
    }
    // merge halves
    a.x += __shfl_xor_sync(0xFFFFFFFFu, a.x, 16);
    a.y += __shfl_xor_sync(0xFFFFFFFFu, a.y, 16);
    a.z += __shfl_xor_sync(0xFFFFFFFFu, a.z, 16);
    a.w += __shfl_xor_sync(0xFFFFFFFFu, a.w, 16);

    if (half == 0) {
        if (do_relu) {
            a.x = fmaxf(a.x, 0.f);
            a.y = fmaxf(a.y, 0.f);
            a.z = fmaxf(a.z, 0.f);
            a.w = fmaxf(a.w, 0.f);
        }
        *(float4*)(OUT + (size_t)node * HID + l) = a;
    }
}

extern "C" void kernel_launch(void* const* d_in, const int* in_sizes, int n_in,
                              void* d_out, int out_size) {
    const float* x  = (const float*)d_in[0];
    const int*   ei = (const int*)d_in[1];   // [2, E]: src row then dst row
    const float* W1 = (const float*)d_in[2];
    const float* b1 = (const float*)d_in[3];
    const float* W2 = (const float*)d_in[4];
    const float* b2 = (const float*)d_in[5];
    float* out = (float*)d_out;
    const int* src = ei;
    const int* dst = ei + EE;

    float *ph, *pact;
    uint16_t *w1h, *w1l, *w2h, *w2l;
    cudaGetSymbolAddress((void**)&ph, g_h);
    cudaGetSymbolAddress((void**)&pact, g_act);
    cudaGetSymbolAddress((void**)&w1h, g_wt1h);
    cudaGetSymbolAddress((void**)&w1l, g_wt1l);
    cudaGetSymbolAddress((void**)&w2h, g_wt2h);
    cudaGetSymbolAddress((void**)&w2l, g_wt2l);

    cudaFuncSetAttribute(k_scan, cudaFuncAttributeMaxDynamicSharedMemorySize,
                         NN * (int)sizeof(int));

    // Serial pipeline (stream fork regressed — L2 contention)
    k_prep<<<36, 256>>>(W1, W2);
    k_hist<<<(EE + 255) / 256, 256>>>(dst);      // g_cnt zeroed by prior k_fill
    k_scan<<<1, 1024, NN * sizeof(int)>>>();
    k_fill<<<(EE + 255) / 256, 256>>>(src, dst); // re-zeros g_cnt at the end

    // Layer 1
    k_gemm<<<(NN + 63) / 64, 128>>>(x, w1h, w1l, ph, NN, 512);
    k_agg<<<(NN * 32 + 255) / 256, 256>>>(ph, b1, pact, 1);
    // Layer 2
    k_gemm<<<(NN + 63) / 64, 128>>>(pact, w2h, w2l, ph, NN, HID);
    k_agg<<<(NN * 32 + 255) / 256, 256>>>(ph, b2, out, 0);
}